// round 11
// baseline (speedup 1.0000x reference)
#include <cuda_runtime.h>
#include <cuda_fp16.h>

#define NN   100000
#define EE   3200000
#define HIDD 128
#define SBLK 196   // scan blocks: 196*512 = 100352 >= NN

// Scratch (allocation-free rule: __device__ globals)
__device__ uint2  g_h[(size_t)NN * 32];        // 25.6 MB: h in fp16 (4 halves/lane)
__device__ float2 g_dc[NN];                    // (.x = cnt as float, .y = weighted deg), memset 0
__device__ float  g_dinv[NN];
__device__ int2   g_rc[EE];                    // packed (row, col) int32
__device__ int    g_cnt[NN];                   // incoming-edge count (int, from scan)
__device__ int    g_start[NN];                 // CSR row start (by target)
__device__ int    g_cursor[NN];                // fill cursor
__device__ unsigned long long g_csr[EE + 64];  // packed (row:int32, norm:f32); pad stays 0
__device__ unsigned long long g_desc[SBLK];    // lookback: (flag<<32)|value (memset 0)

// ---------------------------------------------------------------------------
// L2 eviction-priority via createpolicy + cache_hint (legal for any width on
// sm_80+; the bare .L2::evict_last qualifier only encodes on 256-bit ops).
// Keep g_h resident (evict_last), let streaming traffic (csr, out) use .cs.
__device__ __forceinline__ unsigned long long evl_policy() {
    unsigned long long pol;
    asm("createpolicy.fractional.L2::evict_last.b64 %0, 1.0;" : "=l"(pol));
    return pol;
}
__device__ __forceinline__ uint2 ldg_h_evl(const uint2* p, unsigned long long pol) {
    uint2 u;
    asm volatile("ld.global.nc.L2::cache_hint.v2.u32 {%0,%1}, [%2], %3;"
                 : "=r"(u.x), "=r"(u.y) : "l"(p), "l"(pol));
    return u;
}
__device__ __forceinline__ void stg_h_evl(uint2* p, uint2 u, unsigned long long pol) {
    asm volatile("st.global.L2::cache_hint.v2.u32 [%0], {%1,%2}, %3;"
                 :: "l"(p), "r"(u.x), "r"(u.y), "l"(pol) : "memory");
}

// ---------------------------------------------------------------------------
// prep: dtype probe (per-block), index conversion, fused (cnt, deg) RED.v2.
// int32 buffer read as u64 packs two indices -> >= NN with prob ~1-1e-5/sample.
__global__ void k_prep(const void* __restrict__ ei, const float* __restrict__ ew) {
    __shared__ int s_is64;
    if (threadIdx.x == 0) {
        const unsigned long long* p = (const unsigned long long*)ei;
        int ok = 1;
        for (int j = 0; j < 8; j++)
            if (p[j] >= (unsigned long long)NN) ok = 0;
        s_is64 = ok;
    }
    __syncthreads();
    int is64 = s_is64;
    int stride = gridDim.x * blockDim.x;
    for (int e = blockIdx.x * blockDim.x + threadIdx.x; e < EE; e += stride) {
        int row, col;
        if (is64) {
            row = (int)__ldcs((const long long*)ei + e);
            col = (int)__ldcs((const long long*)ei + (size_t)EE + e);
        } else {
            row = __ldcs((const int*)ei + e);
            col = __ldcs((const int*)ei + (size_t)EE + e);
        }
        __stcs(&g_rc[e], make_int2(row, col));
        float w = __ldcs(ew + e);
        asm volatile("red.global.add.v2.f32 [%0], {%1, %2};"
                     :: "l"(&g_dc[col]), "f"(1.0f), "f"(w) : "memory");
    }
}

// ---------------------------------------------------------------------------
// Single-pass exclusive scan of cnt -> g_start/g_cursor via decoupled lookback
// (flag 0=invalid, 1=aggregate, 2=inclusive-prefix; one 64-bit word per block).
// Also computes dinv = rsqrt(deg+1) and materializes int cnt.
__global__ void __launch_bounds__(512) k_scan() {
    __shared__ int ss[512];
    __shared__ int s_prefix;
    int tid = threadIdx.x, b = blockIdx.x;
    int node = b * 512 + tid;
    int c = 0;
    if (node < NN) {
        float2 dc = g_dc[node];
        c = (int)dc.x;                                   // counts <= 2^24: exact
        g_cnt[node]  = c;
        g_dinv[node] = rsqrtf(dc.y + 1.0f);              // self-loop +1
    }

    ss[tid] = c;
    __syncthreads();
    for (int off = 1; off < 512; off <<= 1) {
        int v = ss[tid];
        int a = (tid >= off) ? ss[tid - off] : 0;
        __syncthreads();
        ss[tid] = v + a;
        __syncthreads();
    }
    int incl = ss[tid];
    int excl = incl - c;
    int total = ss[511];

    if (tid == 0) {
        if (b == 0) {
            atomicExch(&g_desc[0], (2ULL << 32) | (unsigned)total);
            s_prefix = 0;
        } else {
            atomicExch(&g_desc[b], (1ULL << 32) | (unsigned)total);
            int pre = 0;
            for (int j = b - 1; j >= 0; j--) {
                unsigned long long d;
                do { d = atomicAdd(&g_desc[j], 0ULL); } while ((d >> 32) == 0ULL);
                pre += (int)(unsigned)d;
                if ((d >> 32) == 2ULL) break;
            }
            atomicExch(&g_desc[b], (2ULL << 32) | (unsigned)(pre + total));
            s_prefix = pre;
        }
    }
    __syncthreads();
    if (node < NN) {
        int st = s_prefix + excl;
        g_start[node] = st;
        g_cursor[node] = st;
    }
}

// ---------------------------------------------------------------------------
// CSR fill: pack (row, norm) per edge into the target node's segment.
__global__ void k_fill(const float* __restrict__ ew) {
    int stride = gridDim.x * blockDim.x;
    for (int e = blockIdx.x * blockDim.x + threadIdx.x; e < EE; e += stride) {
        int2 rc = __ldcs(&g_rc[e]);
        float norm = g_dinv[rc.x] * __ldcs(ew + e) * g_dinv[rc.y];
        int pos = atomicAdd(&g_cursor[rc.y], 1);
        unsigned long long p = (unsigned int)rc.x
                             | ((unsigned long long)__float_as_uint(norm) << 32);
        __stcs(&g_csr[pos], p);
    }
}

// ---------------------------------------------------------------------------
// GEMM: h[n][o] = sum_k x[n][k] * W[o][k], fp32 accum, fp16 store (one rounding),
// stored with evict_last policy so the table stays L2-resident for the gather.
__global__ void k_gemm(const float* __restrict__ x, const float* __restrict__ W) {
    extern __shared__ float sm[];
    float* Ws = sm;                 // [128][128] transposed
    float* xs = sm + 128 * 128;     // [32][128]
    int tid = threadIdx.x;

    for (int idx = tid; idx < 128 * 128; idx += 256) {
        int o = idx >> 7, k = idx & 127;
        Ws[k * 128 + o] = W[idx];
    }
    int row0 = blockIdx.x * 32;
    const float4* x4 = (const float4*)(x + (size_t)row0 * 128);
    float4* xs4 = (float4*)xs;
    for (int idx = tid; idx < 32 * 32; idx += 256) xs4[idx] = x4[idx];
    __syncthreads();

    int warp = tid >> 5, lane = tid & 31;
    const float* xr0 = xs + (warp * 4 + 0) * 128;
    const float* xr1 = xs + (warp * 4 + 1) * 128;
    const float* xr2 = xs + (warp * 4 + 2) * 128;
    const float* xr3 = xs + (warp * 4 + 3) * 128;

    float4 acc0 = make_float4(0.f, 0.f, 0.f, 0.f);
    float4 acc1 = acc0, acc2 = acc0, acc3 = acc0;

#pragma unroll 8
    for (int k = 0; k < 128; k++) {
        float4 w = *(const float4*)(Ws + k * 128 + lane * 4);
        float a0 = xr0[k], a1 = xr1[k], a2 = xr2[k], a3 = xr3[k];
        acc0.x += a0 * w.x; acc0.y += a0 * w.y; acc0.z += a0 * w.z; acc0.w += a0 * w.w;
        acc1.x += a1 * w.x; acc1.y += a1 * w.y; acc1.z += a1 * w.z; acc1.w += a1 * w.w;
        acc2.x += a2 * w.x; acc2.y += a2 * w.y; acc2.z += a2 * w.z; acc2.w += a2 * w.w;
        acc3.x += a3 * w.x; acc3.y += a3 * w.y; acc3.z += a3 * w.z; acc3.w += a3 * w.w;
    }

    unsigned long long pol = evl_policy();
    size_t base = ((size_t)row0 + warp * 4) * 32 + lane;
    __half2 lo, hi;
    uint2 u;
    lo = __floats2half2_rn(acc0.x, acc0.y); hi = __floats2half2_rn(acc0.z, acc0.w);
    u.x = *(unsigned*)&lo; u.y = *(unsigned*)&hi; stg_h_evl(&g_h[base], u, pol);
    lo = __floats2half2_rn(acc1.x, acc1.y); hi = __floats2half2_rn(acc1.z, acc1.w);
    u.x = *(unsigned*)&lo; u.y = *(unsigned*)&hi; stg_h_evl(&g_h[base + 32], u, pol);
    lo = __floats2half2_rn(acc2.x, acc2.y); hi = __floats2half2_rn(acc2.z, acc2.w);
    u.x = *(unsigned*)&lo; u.y = *(unsigned*)&hi; stg_h_evl(&g_h[base + 64], u, pol);
    lo = __floats2half2_rn(acc3.x, acc3.y); hi = __floats2half2_rn(acc3.z, acc3.w);
    u.x = *(unsigned*)&lo; u.y = *(unsigned*)&hi; stg_h_evl(&g_h[base + 96], u, pol);
}

// ---------------------------------------------------------------------------
// Gather + bias + self-loop + PReLU, one warp per node, 8-deep MLP over edges.
__device__ __forceinline__ void acc_h(float4& acc, float n, uint2 u) {
    __half2 lo = *(__half2*)&u.x, hi = *(__half2*)&u.y;
    float2 f01 = __half22float2(lo), f23 = __half22float2(hi);
    acc.x += n * f01.x; acc.y += n * f01.y;
    acc.z += n * f23.x; acc.w += n * f23.y;
}

__global__ void __launch_bounds__(256) k_gather(const float* __restrict__ bias,
                                                const float* __restrict__ alpha,
                                                float4* __restrict__ out4) {
    int lane = threadIdx.x & 31;
    int node = blockIdx.x * (blockDim.x >> 5) + (threadIdx.x >> 5);
    if (node >= NN) return;

    unsigned long long pol = evl_policy();
    float d = g_dinv[node];
    float d2 = d * d;

    float4 b = ((const float4*)bias)[lane];
    float4 acc = make_float4(0.f, 0.f, 0.f, 0.f);
    acc_h(acc, d2, ldg_h_evl(&g_h[(size_t)node * 32 + lane], pol));
    acc.x += b.x; acc.y += b.y; acc.z += b.z; acc.w += b.w;

    int start = g_start[node];
    int cnt   = g_cnt[node];

    if (cnt > 0) {
        // 8-deep software pipeline; pad region (zero) makes over-reads safe,
        // predication masks out-of-range entries (their h rows are valid).
        unsigned long long p[8], q[8];
#pragma unroll
        for (int i = 0; i < 8; i++) p[i] = __ldcs(&g_csr[start + i]);
        for (int k = 0; k < cnt; k += 8) {
#pragma unroll
            for (int i = 0; i < 8; i++) q[i] = __ldcs(&g_csr[start + k + 8 + i]);

            uint2 v[8];
#pragma unroll
            for (int i = 0; i < 8; i++)
                v[i] = ldg_h_evl(&g_h[(size_t)(unsigned int)p[i] * 32 + lane], pol);

#pragma unroll
            for (int i = 0; i < 8; i++) {
                float n = (k + i < cnt)
                        ? __uint_as_float((unsigned int)(p[i] >> 32)) : 0.f;
                acc_h(acc, n, v[i]);
            }
#pragma unroll
            for (int i = 0; i < 8; i++) p[i] = q[i];
        }
    }

    float4 a = ((const float4*)alpha)[lane];
    acc.x = acc.x > 0.f ? acc.x : a.x * acc.x;
    acc.y = acc.y > 0.f ? acc.y : a.y * acc.y;
    acc.z = acc.z > 0.f ? acc.z : a.z * acc.z;
    acc.w = acc.w > 0.f ? acc.w : a.w * acc.w;
    __stcs(&out4[(size_t)node * 32 + lane], acc);   // streaming: keep h in L2
}

// ---------------------------------------------------------------------------
extern "C" void kernel_launch(void* const* d_in, const int* in_sizes, int n_in,
                              void* d_out, int out_size) {
    const float* x     = (const float*)d_in[0];
    const void*  ei    = d_in[1];
    const float* ew    = (const float*)d_in[2];
    const float* W     = (const float*)d_in[3];
    const float* bias  = (const float*)d_in[4];
    const float* alpha = (const float*)d_in[5];
    float* out = (float*)d_out;

    (void)in_sizes; (void)n_in; (void)out_size;

    static cudaStream_t s1 = nullptr;
    static cudaEvent_t  ev_fork = nullptr, ev_join = nullptr;
    static void *p_dc = nullptr, *p_desc = nullptr;
    if (s1 == nullptr) {
        cudaStreamCreateWithFlags(&s1, cudaStreamNonBlocking);
        cudaEventCreateWithFlags(&ev_fork, cudaEventDisableTiming);
        cudaEventCreateWithFlags(&ev_join, cudaEventDisableTiming);
        cudaFuncSetAttribute(k_gemm, cudaFuncAttributeMaxDynamicSharedMemorySize,
                             80 * 1024);
        cudaGetSymbolAddress(&p_dc,   g_dc);
        cudaGetSymbolAddress(&p_desc, g_desc);
    }

    // Fork: GEMM on s1, overlapped with the CSR-build chain below. (launch #1)
    cudaEventRecord(ev_fork, 0);
    cudaStreamWaitEvent(s1, ev_fork, 0);
    k_gemm<<<NN / 32, 256, 80 * 1024, s1>>>(x, W);   // 100000 % 32 == 0
    cudaEventRecord(ev_join, s1);

    // State reset via memsets (not kernel launches).
    cudaMemsetAsync(p_dc,   0, (size_t)NN * 8, 0);
    cudaMemsetAsync(p_desc, 0, (size_t)SBLK * 8, 0);

    k_prep<<<2048, 256>>>(ei, ew);        // launch #2
    k_scan<<<SBLK, 512>>>();              // launch #3
    k_fill<<<2048, 256>>>(ew);            // launch #4  <- ncu capture slot

    // Join: gather needs both h (s1) and the CSR (main stream).
    cudaStreamWaitEvent(0, ev_join, 0);
    k_gather<<<(NN + 7) / 8, 256>>>(bias, alpha, (float4*)out);   // launch #5
}

// round 12
// speedup vs baseline: 1.0001x; 1.0001x over previous
#include <cuda_runtime.h>
#include <cuda_fp16.h>

#define NN   100000
#define EE   3200000
#define HIDD 128
#define SBLK 196   // scan blocks: 196*512 = 100352 >= NN

// Scratch (allocation-free rule: __device__ globals)
__device__ uint2  g_h[(size_t)NN * 32];        // 25.6 MB: h in fp16 (4 halves/lane)
__device__ float2 g_dc[NN];                    // (.x = cnt as float, .y = weighted deg), memset 0
__device__ float  g_dinv[NN];
__device__ int2   g_rc[EE];                    // packed (row, col) int32
__device__ int    g_cnt[NN];                   // incoming-edge count (int, from scan)
__device__ int    g_start[NN];                 // CSR row start (by target)
__device__ int    g_cursor[NN];                // fill cursor
__device__ unsigned long long g_csr[EE + 64];  // packed (row:int32, norm:f32); pad stays 0
__device__ unsigned long long g_desc[SBLK];    // lookback: (flag<<32)|value (memset 0)

// ---------------------------------------------------------------------------
// L2 eviction-priority via createpolicy + cache_hint.
__device__ __forceinline__ unsigned long long evl_policy() {
    unsigned long long pol;
    asm("createpolicy.fractional.L2::evict_last.b64 %0, 1.0;" : "=l"(pol));
    return pol;
}
__device__ __forceinline__ uint2 ldg_h_evl(const uint2* p, unsigned long long pol) {
    uint2 u;
    asm volatile("ld.global.nc.L2::cache_hint.v2.u32 {%0,%1}, [%2], %3;"
                 : "=r"(u.x), "=r"(u.y) : "l"(p), "l"(pol));
    return u;
}
__device__ __forceinline__ void stg_h_evl(uint2* p, uint2 u, unsigned long long pol) {
    asm volatile("st.global.L2::cache_hint.v2.u32 [%0], {%1,%2}, %3;"
                 :: "l"(p), "r"(u.x), "r"(u.y), "l"(pol) : "memory");
}

// ---------------------------------------------------------------------------
// prep: dtype probe (per-block), index conversion, fused (cnt, deg) RED.v2.
__global__ void k_prep(const void* __restrict__ ei, const float* __restrict__ ew) {
    __shared__ int s_is64;
    if (threadIdx.x == 0) {
        const unsigned long long* p = (const unsigned long long*)ei;
        int ok = 1;
        for (int j = 0; j < 8; j++)
            if (p[j] >= (unsigned long long)NN) ok = 0;
        s_is64 = ok;
    }
    __syncthreads();
    int is64 = s_is64;
    int stride = gridDim.x * blockDim.x;
    for (int e = blockIdx.x * blockDim.x + threadIdx.x; e < EE; e += stride) {
        int row, col;
        if (is64) {
            row = (int)__ldcs((const long long*)ei + e);
            col = (int)__ldcs((const long long*)ei + (size_t)EE + e);
        } else {
            row = __ldcs((const int*)ei + e);
            col = __ldcs((const int*)ei + (size_t)EE + e);
        }
        __stcs(&g_rc[e], make_int2(row, col));
        float w = __ldcs(ew + e);
        asm volatile("red.global.add.v2.f32 [%0], {%1, %2};"
                     :: "l"(&g_dc[col]), "f"(1.0f), "f"(w) : "memory");
    }
}

// ---------------------------------------------------------------------------
// Single-pass exclusive scan of cnt -> g_start/g_cursor via decoupled lookback.
// Also computes dinv = rsqrt(deg+1) and materializes int cnt.
__global__ void __launch_bounds__(512) k_scan() {
    __shared__ int ss[512];
    __shared__ int s_prefix;
    int tid = threadIdx.x, b = blockIdx.x;
    int node = b * 512 + tid;
    int c = 0;
    if (node < NN) {
        float2 dc = g_dc[node];
        c = (int)dc.x;                                   // counts <= 2^24: exact
        g_cnt[node]  = c;
        g_dinv[node] = rsqrtf(dc.y + 1.0f);              // self-loop +1
    }

    ss[tid] = c;
    __syncthreads();
    for (int off = 1; off < 512; off <<= 1) {
        int v = ss[tid];
        int a = (tid >= off) ? ss[tid - off] : 0;
        __syncthreads();
        ss[tid] = v + a;
        __syncthreads();
    }
    int incl = ss[tid];
    int excl = incl - c;
    int total = ss[511];

    if (tid == 0) {
        if (b == 0) {
            atomicExch(&g_desc[0], (2ULL << 32) | (unsigned)total);
            s_prefix = 0;
        } else {
            atomicExch(&g_desc[b], (1ULL << 32) | (unsigned)total);
            int pre = 0;
            for (int j = b - 1; j >= 0; j--) {
                unsigned long long d;
                do { d = atomicAdd(&g_desc[j], 0ULL); } while ((d >> 32) == 0ULL);
                pre += (int)(unsigned)d;
                if ((d >> 32) == 2ULL) break;
            }
            atomicExch(&g_desc[b], (2ULL << 32) | (unsigned)(pre + total));
            s_prefix = pre;
        }
    }
    __syncthreads();
    if (node < NN) {
        int st = s_prefix + excl;
        g_start[node] = st;
        g_cursor[node] = st;
    }
}

// ---------------------------------------------------------------------------
// CSR fill: pack (row, norm) per edge into the target node's segment.
__global__ void k_fill(const float* __restrict__ ew) {
    int stride = gridDim.x * blockDim.x;
    for (int e = blockIdx.x * blockDim.x + threadIdx.x; e < EE; e += stride) {
        int2 rc = __ldcs(&g_rc[e]);
        float norm = g_dinv[rc.x] * __ldcs(ew + e) * g_dinv[rc.y];
        int pos = atomicAdd(&g_cursor[rc.y], 1);
        unsigned long long p = (unsigned int)rc.x
                             | ((unsigned long long)__float_as_uint(norm) << 32);
        __stcs(&g_csr[pos], p);
    }
}

// ---------------------------------------------------------------------------
// GEMM: h[n][o] = sum_k x[n][k] * W[o][k], fp32 accum, fp16 store.
__global__ void k_gemm(const float* __restrict__ x, const float* __restrict__ W) {
    extern __shared__ float sm[];
    float* Ws = sm;                 // [128][128] transposed
    float* xs = sm + 128 * 128;     // [32][128]
    int tid = threadIdx.x;

    for (int idx = tid; idx < 128 * 128; idx += 256) {
        int o = idx >> 7, k = idx & 127;
        Ws[k * 128 + o] = W[idx];
    }
    int row0 = blockIdx.x * 32;
    const float4* x4 = (const float4*)(x + (size_t)row0 * 128);
    float4* xs4 = (float4*)xs;
    for (int idx = tid; idx < 32 * 32; idx += 256) xs4[idx] = x4[idx];
    __syncthreads();

    int warp = tid >> 5, lane = tid & 31;
    const float* xr0 = xs + (warp * 4 + 0) * 128;
    const float* xr1 = xs + (warp * 4 + 1) * 128;
    const float* xr2 = xs + (warp * 4 + 2) * 128;
    const float* xr3 = xs + (warp * 4 + 3) * 128;

    float4 acc0 = make_float4(0.f, 0.f, 0.f, 0.f);
    float4 acc1 = acc0, acc2 = acc0, acc3 = acc0;

#pragma unroll 8
    for (int k = 0; k < 128; k++) {
        float4 w = *(const float4*)(Ws + k * 128 + lane * 4);
        float a0 = xr0[k], a1 = xr1[k], a2 = xr2[k], a3 = xr3[k];
        acc0.x += a0 * w.x; acc0.y += a0 * w.y; acc0.z += a0 * w.z; acc0.w += a0 * w.w;
        acc1.x += a1 * w.x; acc1.y += a1 * w.y; acc1.z += a1 * w.z; acc1.w += a1 * w.w;
        acc2.x += a2 * w.x; acc2.y += a2 * w.y; acc2.z += a2 * w.z; acc2.w += a2 * w.w;
        acc3.x += a3 * w.x; acc3.y += a3 * w.y; acc3.z += a3 * w.z; acc3.w += a3 * w.w;
    }

    unsigned long long pol = evl_policy();
    size_t base = ((size_t)row0 + warp * 4) * 32 + lane;
    __half2 lo, hi;
    uint2 u;
    lo = __floats2half2_rn(acc0.x, acc0.y); hi = __floats2half2_rn(acc0.z, acc0.w);
    u.x = *(unsigned*)&lo; u.y = *(unsigned*)&hi; stg_h_evl(&g_h[base], u, pol);
    lo = __floats2half2_rn(acc1.x, acc1.y); hi = __floats2half2_rn(acc1.z, acc1.w);
    u.x = *(unsigned*)&lo; u.y = *(unsigned*)&hi; stg_h_evl(&g_h[base + 32], u, pol);
    lo = __floats2half2_rn(acc2.x, acc2.y); hi = __floats2half2_rn(acc2.z, acc2.w);
    u.x = *(unsigned*)&lo; u.y = *(unsigned*)&hi; stg_h_evl(&g_h[base + 64], u, pol);
    lo = __floats2half2_rn(acc3.x, acc3.y); hi = __floats2half2_rn(acc3.z, acc3.w);
    u.x = *(unsigned*)&lo; u.y = *(unsigned*)&hi; stg_h_evl(&g_h[base + 96], u, pol);
}

// ---------------------------------------------------------------------------
// Gather + bias + self-loop + PReLU, one warp per node, 8-deep MLP over edges.
// (Byte-identical logic to R11 — this round is about MEASURING it.)
__device__ __forceinline__ void acc_h(float4& acc, float n, uint2 u) {
    __half2 lo = *(__half2*)&u.x, hi = *(__half2*)&u.y;
    float2 f01 = __half22float2(lo), f23 = __half22float2(hi);
    acc.x += n * f01.x; acc.y += n * f01.y;
    acc.z += n * f23.x; acc.w += n * f23.y;
}

__global__ void __launch_bounds__(256) k_gather(const float* __restrict__ bias,
                                                const float* __restrict__ alpha,
                                                float4* __restrict__ out4) {
    int lane = threadIdx.x & 31;
    int node = blockIdx.x * (blockDim.x >> 5) + (threadIdx.x >> 5);
    if (node >= NN) return;

    unsigned long long pol = evl_policy();
    float d = g_dinv[node];
    float d2 = d * d;

    float4 b = ((const float4*)bias)[lane];
    float4 acc = make_float4(0.f, 0.f, 0.f, 0.f);
    acc_h(acc, d2, ldg_h_evl(&g_h[(size_t)node * 32 + lane], pol));
    acc.x += b.x; acc.y += b.y; acc.z += b.z; acc.w += b.w;

    int start = g_start[node];
    int cnt   = g_cnt[node];

    if (cnt > 0) {
        unsigned long long p[8], q[8];
#pragma unroll
        for (int i = 0; i < 8; i++) p[i] = __ldcs(&g_csr[start + i]);
        for (int k = 0; k < cnt; k += 8) {
#pragma unroll
            for (int i = 0; i < 8; i++) q[i] = __ldcs(&g_csr[start + k + 8 + i]);

            uint2 v[8];
#pragma unroll
            for (int i = 0; i < 8; i++)
                v[i] = ldg_h_evl(&g_h[(size_t)(unsigned int)p[i] * 32 + lane], pol);

#pragma unroll
            for (int i = 0; i < 8; i++) {
                float n = (k + i < cnt)
                        ? __uint_as_float((unsigned int)(p[i] >> 32)) : 0.f;
                acc_h(acc, n, v[i]);
            }
#pragma unroll
            for (int i = 0; i < 8; i++) p[i] = q[i];
        }
    }

    float4 a = ((const float4*)alpha)[lane];
    acc.x = acc.x > 0.f ? acc.x : a.x * acc.x;
    acc.y = acc.y > 0.f ? acc.y : a.y * acc.y;
    acc.z = acc.z > 0.f ? acc.z : a.z * acc.z;
    acc.w = acc.w > 0.f ? acc.w : a.w * acc.w;
    __stcs(&out4[(size_t)node * 32 + lane], acc);
}

// ---------------------------------------------------------------------------
extern "C" void kernel_launch(void* const* d_in, const int* in_sizes, int n_in,
                              void* d_out, int out_size) {
    const float* x     = (const float*)d_in[0];
    const void*  ei    = d_in[1];
    const float* ew    = (const float*)d_in[2];
    const float* W     = (const float*)d_in[3];
    const float* bias  = (const float*)d_in[4];
    const float* alpha = (const float*)d_in[5];
    float* out = (float*)d_out;

    (void)in_sizes; (void)n_in; (void)out_size;

    static cudaStream_t s1 = nullptr, s2 = nullptr;
    static cudaEvent_t  ev_fork = nullptr, ev_gemm = nullptr,
                        ev_scan = nullptr, ev_fill = nullptr;
    static void *p_dc = nullptr, *p_desc = nullptr;
    if (s1 == nullptr) {
        cudaStreamCreateWithFlags(&s1, cudaStreamNonBlocking);
        cudaStreamCreateWithFlags(&s2, cudaStreamNonBlocking);
        cudaEventCreateWithFlags(&ev_fork, cudaEventDisableTiming);
        cudaEventCreateWithFlags(&ev_gemm, cudaEventDisableTiming);
        cudaEventCreateWithFlags(&ev_scan, cudaEventDisableTiming);
        cudaEventCreateWithFlags(&ev_fill, cudaEventDisableTiming);
        cudaFuncSetAttribute(k_gemm, cudaFuncAttributeMaxDynamicSharedMemorySize,
                             80 * 1024);
        cudaGetSymbolAddress(&p_dc,   g_dc);
        cudaGetSymbolAddress(&p_desc, g_desc);
    }

    // Fork: GEMM on s1 (side-stream launches don't consume capture slots).
    cudaEventRecord(ev_fork, 0);
    cudaStreamWaitEvent(s1, ev_fork, 0);
    k_gemm<<<NN / 32, 256, 80 * 1024, s1>>>(x, W);   // 100000 % 32 == 0
    cudaEventRecord(ev_gemm, s1);

    // State reset via memsets (graph memset nodes, not kernel launches).
    cudaMemsetAsync(p_dc,   0, (size_t)NN * 8, 0);
    cudaMemsetAsync(p_desc, 0, (size_t)SBLK * 8, 0);

    k_prep<<<2048, 256>>>(ei, ew);        // main launch 1
    k_scan<<<SBLK, 512>>>();              // main launch 2
    cudaEventRecord(ev_scan, 0);

    // Fill on s2: depends only on scan; runs under the GEMM window as before.
    cudaStreamWaitEvent(s2, ev_scan, 0);
    k_fill<<<2048, 256, 0, s2>>>(ew);
    cudaEventRecord(ev_fill, s2);

    // Join: gather needs h (s1) and the CSR (s2).
    cudaStreamWaitEvent(0, ev_gemm, 0);
    cudaStreamWaitEvent(0, ev_fill, 0);
    k_gather<<<(NN + 7) / 8, 256>>>(bias, alpha, (float4*)out);  // main launch 3 <- ncu
}

// round 13
// speedup vs baseline: 1.6539x; 1.6537x over previous
#include <cuda_runtime.h>
#include <cuda_fp16.h>
#include <mma.h>

using namespace nvcuda;

#define NN   100000
#define EE   3200000
#define HIDD 128
#define SBLK 196   // scan blocks: 196*512 = 100352 >= NN
#define GEMM_BLOCKS ((NN + 127) / 128)   // 782

// Scratch (allocation-free rule: __device__ globals)
__device__ uint2  g_h[(size_t)NN * 32];        // 25.6 MB: h in fp16 (4 halves/lane)
__device__ float2 g_dc[NN];                    // (.x = cnt as float, .y = weighted deg), memset 0
__device__ float  g_dinv[NN];
__device__ int2   g_rc[EE];                    // packed (row, col) int32
__device__ int    g_cnt[NN];                   // incoming-edge count (int, from scan)
__device__ int    g_start[NN];                 // CSR row start (by target)
__device__ int    g_cursor[NN];                // fill cursor
__device__ unsigned long long g_csr[EE + 64];  // packed (row:int32, norm:f32); pad stays 0
__device__ unsigned long long g_desc[SBLK];    // lookback: (flag<<32)|value (memset 0)

// ---------------------------------------------------------------------------
// L2 eviction-priority via createpolicy + cache_hint.
__device__ __forceinline__ unsigned long long evl_policy() {
    unsigned long long pol;
    asm("createpolicy.fractional.L2::evict_last.b64 %0, 1.0;" : "=l"(pol));
    return pol;
}
__device__ __forceinline__ uint2 ldg_h_evl(const uint2* p, unsigned long long pol) {
    uint2 u;
    asm volatile("ld.global.nc.L2::cache_hint.v2.u32 {%0,%1}, [%2], %3;"
                 : "=r"(u.x), "=r"(u.y) : "l"(p), "l"(pol));
    return u;
}
__device__ __forceinline__ void stg_h_evl(uint2* p, uint2 u, unsigned long long pol) {
    asm volatile("st.global.L2::cache_hint.v2.u32 [%0], {%1,%2}, %3;"
                 :: "l"(p), "r"(u.x), "r"(u.y), "l"(pol) : "memory");
}

// ---------------------------------------------------------------------------
// prep: dtype probe (per-block), index conversion, fused (cnt, deg) RED.v2.
__global__ void k_prep(const void* __restrict__ ei, const float* __restrict__ ew) {
    __shared__ int s_is64;
    if (threadIdx.x == 0) {
        const unsigned long long* p = (const unsigned long long*)ei;
        int ok = 1;
        for (int j = 0; j < 8; j++)
            if (p[j] >= (unsigned long long)NN) ok = 0;
        s_is64 = ok;
    }
    __syncthreads();
    int is64 = s_is64;
    int stride = gridDim.x * blockDim.x;
    for (int e = blockIdx.x * blockDim.x + threadIdx.x; e < EE; e += stride) {
        int row, col;
        if (is64) {
            row = (int)__ldcs((const long long*)ei + e);
            col = (int)__ldcs((const long long*)ei + (size_t)EE + e);
        } else {
            row = __ldcs((const int*)ei + e);
            col = __ldcs((const int*)ei + (size_t)EE + e);
        }
        __stcs(&g_rc[e], make_int2(row, col));
        float w = __ldcs(ew + e);
        asm volatile("red.global.add.v2.f32 [%0], {%1, %2};"
                     :: "l"(&g_dc[col]), "f"(1.0f), "f"(w) : "memory");
    }
}

// ---------------------------------------------------------------------------
// Single-pass exclusive scan of cnt -> g_start/g_cursor via decoupled lookback.
// Also computes dinv = rsqrt(deg+1) and materializes int cnt.
__global__ void __launch_bounds__(512) k_scan() {
    __shared__ int ss[512];
    __shared__ int s_prefix;
    int tid = threadIdx.x, b = blockIdx.x;
    int node = b * 512 + tid;
    int c = 0;
    if (node < NN) {
        float2 dc = g_dc[node];
        c = (int)dc.x;                                   // counts <= 2^24: exact
        g_cnt[node]  = c;
        g_dinv[node] = rsqrtf(dc.y + 1.0f);              // self-loop +1
    }

    ss[tid] = c;
    __syncthreads();
    for (int off = 1; off < 512; off <<= 1) {
        int v = ss[tid];
        int a = (tid >= off) ? ss[tid - off] : 0;
        __syncthreads();
        ss[tid] = v + a;
        __syncthreads();
    }
    int incl = ss[tid];
    int excl = incl - c;
    int total = ss[511];

    if (tid == 0) {
        if (b == 0) {
            atomicExch(&g_desc[0], (2ULL << 32) | (unsigned)total);
            s_prefix = 0;
        } else {
            atomicExch(&g_desc[b], (1ULL << 32) | (unsigned)total);
            int pre = 0;
            for (int j = b - 1; j >= 0; j--) {
                unsigned long long d;
                do { d = atomicAdd(&g_desc[j], 0ULL); } while ((d >> 32) == 0ULL);
                pre += (int)(unsigned)d;
                if ((d >> 32) == 2ULL) break;
            }
            atomicExch(&g_desc[b], (2ULL << 32) | (unsigned)(pre + total));
            s_prefix = pre;
        }
    }
    __syncthreads();
    if (node < NN) {
        int st = s_prefix + excl;
        g_start[node] = st;
        g_cursor[node] = st;
    }
}

// ---------------------------------------------------------------------------
// CSR fill: pack (row, norm) per edge into the target node's segment.
__global__ void k_fill(const float* __restrict__ ew) {
    int stride = gridDim.x * blockDim.x;
    for (int e = blockIdx.x * blockDim.x + threadIdx.x; e < EE; e += stride) {
        int2 rc = __ldcs(&g_rc[e]);
        float norm = g_dinv[rc.x] * __ldcs(ew + e) * g_dinv[rc.y];
        int pos = atomicAdd(&g_cursor[rc.y], 1);
        unsigned long long p = (unsigned int)rc.x
                             | ((unsigned long long)__float_as_uint(norm) << 32);
        __stcs(&g_csr[pos], p);
    }
}

// ---------------------------------------------------------------------------
// Tensor-core GEMM: h[n][o] = sum_k x[n][k] * W[o][k].
// 128x128 block tile, 8 warps; warp w owns rows [w*16, w*16+16) x all 128 cols
// = 8 wmma (16x16x16) col-tiles, K loop of 8. fp16 inputs (converted in smem),
// fp32 accum; output staged to smem (reusing x/W tiles) then packed to fp16
// g_h with evict_last. B tile needs no transpose: W row-major [o][k] IS the
// col-major (k x o) operand.
__global__ void __launch_bounds__(256) k_gemm(const float* __restrict__ x,
                                              const float* __restrict__ W) {
    extern __shared__ char smemc[];
    __half* xs = (__half*)smemc;                   // [128][128] fp16, 32 KB
    __half* Ws = (__half*)(smemc + 32 * 1024);     // [128][128] fp16, 32 KB
    float*  cs = (float*)smemc;                    // reused after MMA: 8 strips x 8 KB

    int tid = threadIdx.x;
    int row0 = blockIdx.x * 128;

    for (int i = tid; i < 128 * 128; i += 256)
        Ws[i] = __float2half_rn(W[i]);
    for (int i = tid; i < 128 * 128; i += 256) {
        int r = row0 + (i >> 7);
        float v = (r < NN) ? x[(size_t)r * 128 + (i & 127)] : 0.f;
        xs[i] = __float2half_rn(v);
    }
    __syncthreads();

    int w = tid >> 5;
    wmma::fragment<wmma::accumulator, 16, 16, 16, float> c[8];
#pragma unroll
    for (int j = 0; j < 8; j++) wmma::fill_fragment(c[j], 0.f);

#pragma unroll
    for (int k = 0; k < 8; k++) {
        wmma::fragment<wmma::matrix_a, 16, 16, 16, __half, wmma::row_major> a;
        wmma::load_matrix_sync(a, xs + (w * 16) * 128 + k * 16, 128);
#pragma unroll
        for (int j = 0; j < 8; j++) {
            wmma::fragment<wmma::matrix_b, 16, 16, 16, __half, wmma::col_major> b;
            wmma::load_matrix_sync(b, Ws + (j * 16) * 128 + k * 16, 128);
            wmma::mma_sync(c[j], a, b, c[j]);
        }
    }
    __syncthreads();   // all xs/Ws reads done; safe to reuse as cs

    float* strip = cs + w * 16 * 128;   // warp-private 16x128 f32 strip
#pragma unroll
    for (int j = 0; j < 8; j++)
        wmma::store_matrix_sync(strip + j * 16, c[j], 128, wmma::mem_row_major);
    __syncwarp();

    unsigned long long pol = evl_policy();
    int lane = tid & 31;
    for (int r = 0; r < 16; r++) {
        int row = row0 + w * 16 + r;
        if (row >= NN) break;
        float4 f = ((const float4*)(strip + r * 128))[lane];
        __half2 lo = __floats2half2_rn(f.x, f.y);
        __half2 hi = __floats2half2_rn(f.z, f.w);
        uint2 u;
        u.x = *(unsigned*)&lo; u.y = *(unsigned*)&hi;
        stg_h_evl(&g_h[(size_t)row * 32 + lane], u, pol);
    }
}

// ---------------------------------------------------------------------------
// Gather + bias + self-loop + PReLU, one warp per node, 8-deep MLP over edges.
// (Byte-identical to R11/R12 for clean attribution.)
__device__ __forceinline__ void acc_h(float4& acc, float n, uint2 u) {
    __half2 lo = *(__half2*)&u.x, hi = *(__half2*)&u.y;
    float2 f01 = __half22float2(lo), f23 = __half22float2(hi);
    acc.x += n * f01.x; acc.y += n * f01.y;
    acc.z += n * f23.x; acc.w += n * f23.y;
}

__global__ void __launch_bounds__(256) k_gather(const float* __restrict__ bias,
                                                const float* __restrict__ alpha,
                                                float4* __restrict__ out4) {
    int lane = threadIdx.x & 31;
    int node = blockIdx.x * (blockDim.x >> 5) + (threadIdx.x >> 5);
    if (node >= NN) return;

    unsigned long long pol = evl_policy();
    float d = g_dinv[node];
    float d2 = d * d;

    float4 b = ((const float4*)bias)[lane];
    float4 acc = make_float4(0.f, 0.f, 0.f, 0.f);
    acc_h(acc, d2, ldg_h_evl(&g_h[(size_t)node * 32 + lane], pol));
    acc.x += b.x; acc.y += b.y; acc.z += b.z; acc.w += b.w;

    int start = g_start[node];
    int cnt   = g_cnt[node];

    if (cnt > 0) {
        unsigned long long p[8], q[8];
#pragma unroll
        for (int i = 0; i < 8; i++) p[i] = __ldcs(&g_csr[start + i]);
        for (int k = 0; k < cnt; k += 8) {
#pragma unroll
            for (int i = 0; i < 8; i++) q[i] = __ldcs(&g_csr[start + k + 8 + i]);

            uint2 v[8];
#pragma unroll
            for (int i = 0; i < 8; i++)
                v[i] = ldg_h_evl(&g_h[(size_t)(unsigned int)p[i] * 32 + lane], pol);

#pragma unroll
            for (int i = 0; i < 8; i++) {
                float n = (k + i < cnt)
                        ? __uint_as_float((unsigned int)(p[i] >> 32)) : 0.f;
                acc_h(acc, n, v[i]);
            }
#pragma unroll
            for (int i = 0; i < 8; i++) p[i] = q[i];
        }
    }

    float4 a = ((const float4*)alpha)[lane];
    acc.x = acc.x > 0.f ? acc.x : a.x * acc.x;
    acc.y = acc.y > 0.f ? acc.y : a.y * acc.y;
    acc.z = acc.z > 0.f ? acc.z : a.z * acc.z;
    acc.w = acc.w > 0.f ? acc.w : a.w * acc.w;
    __stcs(&out4[(size_t)node * 32 + lane], acc);
}

// ---------------------------------------------------------------------------
extern "C" void kernel_launch(void* const* d_in, const int* in_sizes, int n_in,
                              void* d_out, int out_size) {
    const float* x     = (const float*)d_in[0];
    const void*  ei    = d_in[1];
    const float* ew    = (const float*)d_in[2];
    const float* W     = (const float*)d_in[3];
    const float* bias  = (const float*)d_in[4];
    const float* alpha = (const float*)d_in[5];
    float* out = (float*)d_out;

    (void)in_sizes; (void)n_in; (void)out_size;

    static cudaStream_t s1 = nullptr, s2 = nullptr;
    static cudaEvent_t  ev_fork = nullptr, ev_gemm = nullptr,
                        ev_scan = nullptr, ev_fill = nullptr;
    static void *p_dc = nullptr, *p_desc = nullptr;
    if (s1 == nullptr) {
        cudaStreamCreateWithFlags(&s1, cudaStreamNonBlocking);
        cudaStreamCreateWithFlags(&s2, cudaStreamNonBlocking);
        cudaEventCreateWithFlags(&ev_fork, cudaEventDisableTiming);
        cudaEventCreateWithFlags(&ev_gemm, cudaEventDisableTiming);
        cudaEventCreateWithFlags(&ev_scan, cudaEventDisableTiming);
        cudaEventCreateWithFlags(&ev_fill, cudaEventDisableTiming);
        cudaFuncSetAttribute(k_gemm, cudaFuncAttributeMaxDynamicSharedMemorySize,
                             64 * 1024);
        cudaGetSymbolAddress(&p_dc,   g_dc);
        cudaGetSymbolAddress(&p_desc, g_desc);
    }

    // Fork: tensor-core GEMM on s1, overlapped with the CSR build.
    cudaEventRecord(ev_fork, 0);
    cudaStreamWaitEvent(s1, ev_fork, 0);
    k_gemm<<<GEMM_BLOCKS, 256, 64 * 1024, s1>>>(x, W);
    cudaEventRecord(ev_gemm, s1);

    // State reset via memsets (graph memset nodes, not kernel launches).
    cudaMemsetAsync(p_dc,   0, (size_t)NN * 8, 0);
    cudaMemsetAsync(p_desc, 0, (size_t)SBLK * 8, 0);

    k_prep<<<2048, 256>>>(ei, ew);
    k_scan<<<SBLK, 512>>>();
    cudaEventRecord(ev_scan, 0);

    // Fill on s2: depends only on scan.
    cudaStreamWaitEvent(s2, ev_scan, 0);
    k_fill<<<2048, 256, 0, s2>>>(ew);
    cudaEventRecord(ev_fill, s2);

    // Join: gather needs h (s1) and the CSR (s2).
    cudaStreamWaitEvent(0, ev_gemm, 0);
    cudaStreamWaitEvent(0, ev_fill, 0);
    k_gather<<<(NN + 7) / 8, 256>>>(bias, alpha, (float4*)out);
}